// round 4
// baseline (speedup 1.0000x reference)
#include <cuda_runtime.h>

// 2-layer LSTM (H=51), B=512, T=512, scalar in, linear head, future=0.
// 128 persistent blocks, BB=4 rows, 640 threads, ONE barrier per step.
// Thread tiling: 4 gates (i,f,g,o of one hidden unit) x 4 batches x 13-k-slice
//   -> 4x less smem broadcast traffic than 1-gate tiling.
// K-split partials reduced via quad shuffle reduce-scatter; combine in-register.
// Layer-2 lags layer-1 by one step; h1/h2 double-buffered (parity swap).

#define H     51
#define HP    56            // padded row stride (floats); pads 51..55 = 0
#define BB    4
#define TT    512
#define NTH   640
#define NBLK  128
#define NITER 514
#define BHP   (BB*HP)       // 224

__device__ __forceinline__ float sigf(float x)     { return 1.0f / (1.0f + __expf(-x)); }
__device__ __forceinline__ float tanhfast(float x) { return 1.0f - 2.0f / (__expf(2.0f*x) + 1.0f); }

// quad reduce-scatter: lanes 4m..4m+3 (q = lane&3) each hold a0..a3 (per-b partials
// over their k-slice); returns sum over the quad of component q.
__device__ __forceinline__ float rs4(float a0, float a1, float a2, float a3,
                                     int q, unsigned mask)
{
    const bool q0 = (q & 1), q1 = (q & 2);
    float kl = q0 ? a1 : a0;     // kept low component (index q&1)
    float sl = q0 ? a0 : a1;     // what my xor-1 partner needs
    float kh = q0 ? a3 : a2;     // kept high component (index 2+(q&1))
    float sh = q0 ? a2 : a3;
    kl += __shfl_xor_sync(mask, sl, 1);
    kh += __shfl_xor_sync(mask, sh, 1);
    float k2 = q1 ? kh : kl;
    float s2 = q1 ? kl : kh;
    return k2 + __shfl_xor_sync(mask, s2, 2);
}

__global__ __launch_bounds__(NTH, 1)
void lstm2_kernel(const float* __restrict__ input,
                  const float* __restrict__ W_ih1,
                  const float* __restrict__ W_hh1,
                  const float* __restrict__ b_ih1,
                  const float* __restrict__ b_hh1,
                  const float* __restrict__ W_ih2,
                  const float* __restrict__ W_hh2,
                  const float* __restrict__ b_ih2,
                  const float* __restrict__ b_hh2,
                  const float* __restrict__ W_lin,
                  const float* __restrict__ b_lin,
                  float* __restrict__ out)
{
    __shared__ float h1s[2][BHP];
    __shared__ float h2s[2][BHP];
    __shared__ float xall[BB*TT];

    const int tid  = threadIdx.x;
    const int lane = tid & 31;
    const int row0 = blockIdx.x * BB;

    // roles: [0,204) L1; [204,212) out-head (warp 6 lanes 12..19); [224,632) L2
    const bool isL1  = (tid < 204);
    const bool isOut = (tid >= 204 && tid < 212);
    const bool isL2  = (tid >= 224 && tid < 632);

    int hh = 0, ks = 0, part = 0;
    if (isL1) { hh = tid >> 2; ks = tid & 3; }
    if (isL2) { const int l = tid - 224; hh = l >> 3; part = (l >> 2) & 1; ks = l & 3; }

    const unsigned qmask = 0xFu  << (lane & 28);
    const unsigned omask = 0xFFu << (lane & 24);
    const unsigned pmask = 0x3u  << (lane & 30);

    // ---- init smem ----
    for (int i = tid; i < BHP; i += NTH) {
        h1s[0][i] = 0.f; h1s[1][i] = 0.f; h2s[0][i] = 0.f; h2s[1][i] = 0.f;
    }
    for (int i = tid; i < BB*TT; i += NTH) {
        const int b = i >> 9;
        const int t = i & (TT - 1);
        xall[i] = input[(row0 + b)*TT + t];
    }

    // ---- per-thread weights ----
    float w[4][13];
    float wx[4] = {0.f,0.f,0.f,0.f}, bz[4] = {0.f,0.f,0.f,0.f};
    if (isL1 || isL2) {
        const float* W = isL1 ? W_hh1 : (part ? W_hh2 : W_ih2);
        #pragma unroll
        for (int g = 0; g < 4; ++g) {
            const int r = hh + 51*g;
            #pragma unroll
            for (int m = 0; m < 13; ++m) {
                const int k = ks*13 + m;
                w[g][m] = (k < H) ? W[r*H + k] : 0.0f;
            }
            if (isL1) {
                wx[g] = W_ih1[r];
                bz[g] = b_ih1[r] + b_hh1[r];
            } else {
                bz[g] = b_ih2[r] + b_hh2[r];   // added once (part==0 path uses it)
            }
        }
    }

    // ---- out-head weights ----
    float wo[26]; float blin = 0.f; int ob = 0, half = 0;
    if (isOut) {
        const int o = tid - 204;
        ob = o >> 1; half = o & 1;
        #pragma unroll
        for (int m = 0; m < 26; ++m) {
            const int j = half*26 + m;
            wo[m] = (j < H) ? W_lin[j] : 0.0f;
        }
        blin = b_lin[0];
    }

    float cst = 0.f;   // c1 for L1 threads, c2 for L2 part==0 threads
    __syncthreads();

    for (int t = 0; t < NITER; ++t) {
        const int p = t & 1;

        if (isL1) {
            if (t < TT) {
                const float* hb = h1s[p];
                float acc[4][4];
                #pragma unroll
                for (int g = 0; g < 4; ++g)
                    { acc[g][0]=0.f; acc[g][1]=0.f; acc[g][2]=0.f; acc[g][3]=0.f; }
                const int k0 = ks*13;
                #pragma unroll
                for (int m = 0; m < 13; ++m) {
                    const float u0 = hb[0*HP + k0 + m];
                    const float u1 = hb[1*HP + k0 + m];
                    const float u2 = hb[2*HP + k0 + m];
                    const float u3 = hb[3*HP + k0 + m];
                    #pragma unroll
                    for (int g = 0; g < 4; ++g) {
                        acc[g][0] = fmaf(w[g][m], u0, acc[g][0]);
                        acc[g][1] = fmaf(w[g][m], u1, acc[g][1]);
                        acc[g][2] = fmaf(w[g][m], u2, acc[g][2]);
                        acc[g][3] = fmaf(w[g][m], u3, acc[g][3]);
                    }
                }
                float z[4];
                #pragma unroll
                for (int g = 0; g < 4; ++g)
                    z[g] = rs4(acc[g][0], acc[g][1], acc[g][2], acc[g][3], ks, qmask);
                const float xv = xall[ks*TT + t];
                #pragma unroll
                for (int g = 0; g < 4; ++g) z[g] += fmaf(xv, wx[g], bz[g]);
                const float ig = sigf(z[0]), fg = sigf(z[1]);
                const float gg = tanhfast(z[2]), og = sigf(z[3]);
                cst = fmaf(fg, cst, ig*gg);
                h1s[p^1][ks*HP + hh] = og * tanhfast(cst);
            }
        } else if (isL2) {
            if (t >= 1 && t <= TT) {
                const float* hb = part ? h2s[p] : h1s[p];
                float acc[4][4];
                #pragma unroll
                for (int g = 0; g < 4; ++g)
                    { acc[g][0]=0.f; acc[g][1]=0.f; acc[g][2]=0.f; acc[g][3]=0.f; }
                const int k0 = ks*13;
                #pragma unroll
                for (int m = 0; m < 13; ++m) {
                    const float u0 = hb[0*HP + k0 + m];
                    const float u1 = hb[1*HP + k0 + m];
                    const float u2 = hb[2*HP + k0 + m];
                    const float u3 = hb[3*HP + k0 + m];
                    #pragma unroll
                    for (int g = 0; g < 4; ++g) {
                        acc[g][0] = fmaf(w[g][m], u0, acc[g][0]);
                        acc[g][1] = fmaf(w[g][m], u1, acc[g][1]);
                        acc[g][2] = fmaf(w[g][m], u2, acc[g][2]);
                        acc[g][3] = fmaf(w[g][m], u3, acc[g][3]);
                    }
                }
                float z[4];
                #pragma unroll
                for (int g = 0; g < 4; ++g) {
                    float zp = rs4(acc[g][0], acc[g][1], acc[g][2], acc[g][3], ks, qmask);
                    zp += __shfl_xor_sync(omask, zp, 4);   // sum Wih2- and Whh2-parts
                    z[g] = zp;
                }
                if (part == 0) {
                    #pragma unroll
                    for (int g = 0; g < 4; ++g) z[g] += bz[g];
                    const float ig = sigf(z[0]), fg = sigf(z[1]);
                    const float gg = tanhfast(z[2]), og = sigf(z[3]);
                    cst = fmaf(fg, cst, ig*gg);
                    h2s[p^1][ks*HP + hh] = og * tanhfast(cst);
                }
            }
        } else if (isOut) {
            if (t >= 2) {
                const float* hb = h2s[p];   // h2(t-2)
                float v = 0.f;
                #pragma unroll
                for (int m = 0; m < 26; ++m)
                    v = fmaf(hb[ob*HP + half*26 + m], wo[m], v);
                v += __shfl_xor_sync(pmask, v, 1);
                if (half == 0) out[(row0 + ob)*TT + (t - 2)] = v + blin;
            }
        }
        __syncthreads();
    }
}

extern "C" void kernel_launch(void* const* d_in, const int* in_sizes, int n_in,
                              void* d_out, int out_size)
{
    const float* input = (const float*)d_in[0];
    const float* W_ih1 = (const float*)d_in[1];
    const float* W_hh1 = (const float*)d_in[2];
    const float* b_ih1 = (const float*)d_in[3];
    const float* b_hh1 = (const float*)d_in[4];
    const float* W_ih2 = (const float*)d_in[5];
    const float* W_hh2 = (const float*)d_in[6];
    const float* b_ih2 = (const float*)d_in[7];
    const float* b_hh2 = (const float*)d_in[8];
    const float* W_lin = (const float*)d_in[9];
    const float* b_lin = (const float*)d_in[10];
    float* out = (float*)d_out;

    lstm2_kernel<<<NBLK, NTH>>>(input, W_ih1, W_hh1, b_ih1, b_hh1,
                                W_ih2, W_hh2, b_ih2, b_hh2,
                                W_lin, b_lin, out);
}

// round 5
// speedup vs baseline: 1.2295x; 1.2295x over previous
#include <cuda_runtime.h>

// 2-layer LSTM (H=51), B=512, T=512, scalar in, linear head, future=0.
// 128 persistent blocks, BB=4 rows, 352 threads (11 warps), ONE barrier/step.
// Thread = 4 gates x 4 batches x k-half; weights in registers (56 f32x2);
// vector LDS.128 h loads (28/thread, conflict-free); shuffle reduce-scatter;
// combine in-register. Layer-2 lags layer-1 by one step (parity buffers).

#define H    51
#define HP   56
#define TT   512
#define NTH  352
#define NBLK 128
#define NITER 514

typedef unsigned long long ull;

__device__ __forceinline__ ull fma2(ull a, ull b, ull c) {
    ull d; asm("fma.rn.f32x2 %0, %1, %2, %3;" : "=l"(d) : "l"(a), "l"(b), "l"(c)); return d;
}
__device__ __forceinline__ ull pack2(float lo, float hi) {
    ull d; asm("mov.b64 %0, {%1, %2};" : "=l"(d) : "f"(lo), "f"(hi)); return d;
}
__device__ __forceinline__ float sum2(ull a) {
    float x, y; asm("mov.b64 {%0, %1}, %2;" : "=f"(x), "=f"(y) : "l"(a)); return x + y;
}
__device__ __forceinline__ float sigf(float x)     { return 1.0f / (1.0f + __expf(-x)); }
__device__ __forceinline__ float tanhfast(float x) { return 1.0f - 2.0f / (__expf(2.0f*x) + 1.0f); }

__global__ __launch_bounds__(NTH, 1)
void lstm2_kernel(const float* __restrict__ input,
                  const float* __restrict__ W_ih1,
                  const float* __restrict__ W_hh1,
                  const float* __restrict__ b_ih1,
                  const float* __restrict__ b_hh1,
                  const float* __restrict__ W_ih2,
                  const float* __restrict__ W_hh2,
                  const float* __restrict__ b_ih2,
                  const float* __restrict__ b_hh2,
                  const float* __restrict__ W_lin,
                  const float* __restrict__ b_lin,
                  float* __restrict__ out)
{
    // hbuf: h1 parity0 [224], h1 parity1 [224], pad[8], h2 parity0, h2 parity1
    // h2 base offset = 456 floats == 8 mod 32 banks -> L2's 4 lane address
    // groups land at banks {0,28,8,4}+4j: conflict-free.
    __shared__ __align__(16) float hbuf[2*4*HP + 8 + 2*4*HP];
    __shared__ float xall[4*TT];

    float* const h1b = hbuf;
    float* const h2b = hbuf + 2*4*HP + 8;

    const int tid  = threadIdx.x;
    const int lane = tid & 31;
    const int row0 = blockIdx.x * 4;

    const bool isL1  = (tid < 102);
    const bool isOut = (tid >= 104 && tid < 112);
    const bool isL2  = (tid >= 128 && tid < 332);

    // ---- init smem ----
    for (int i = tid; i < 2*4*HP + 8 + 2*4*HP; i += NTH) hbuf[i] = 0.0f;
    for (int i = tid; i < 4*TT; i += NTH) {
        const int b = i >> 9;
        const int t = i & (TT - 1);
        xall[i] = input[(row0 + b)*TT + t];
    }

    // ---- role decode ----
    int unit = 0, ks = 0, mat = 0;
    if (isL1)      { unit = tid >> 1; ks = tid & 1; }
    else if (isL2) { const int l2 = tid - 128; unit = l2 >> 2; mat = (l2 >> 1) & 1; ks = l2 & 1; }

    // ---- weights -> registers: 4 gate rows x k-half as f32x2 ----
    ull w2[4][14];
    float bz[4] = {0,0,0,0}, wx[4] = {0,0,0,0};
    if (isL1 || isL2) {
        const float* W = isL1 ? W_hh1 : (mat ? W_hh2 : W_ih2);
        #pragma unroll
        for (int g = 0; g < 4; ++g) {
            const int r = unit + 51*g;
            #pragma unroll
            for (int m = 0; m < 14; ++m) {
                const int k = ks*28 + 2*m;
                const float lo = (k   < H) ? W[r*H + k]     : 0.0f;
                const float hi = (k+1 < H) ? W[r*H + k + 1] : 0.0f;
                w2[g][m] = pack2(lo, hi);
            }
            if (isL1) { bz[g] = b_ih1[r] + b_hh1[r]; wx[g] = W_ih1[r]; }
            else if (!mat) { bz[g] = b_ih2[r] + b_hh2[r]; }  // added by final holder below
        }
    }
    if (isL2) {   // final b = 2*ks + mat; bias must be added exactly once by each final holder
        #pragma unroll
        for (int g = 0; g < 4; ++g) {
            const int r = unit + 51*g;
            bz[g] = b_ih2[r] + b_hh2[r];
        }
    }

    // ---- out-head (warp 3, lanes 8..15): pair (batch, half-of-26) ----
    float wo[26]; float blin = 0.0f; int ob = 0, half = 0;
    if (isOut) {
        const int o = tid - 104;
        ob = o >> 1; half = o & 1;
        #pragma unroll
        for (int m = 0; m < 26; ++m) {
            const int j = half*26 + m;
            wo[m] = (j < H) ? W_lin[j] : 0.0f;
        }
        blin = b_lin[0];
    }

    const unsigned pmask = 0x3u << (lane & 30);
    const unsigned qmask = 0xFu << (lane & 28);

    float c1[2] = {0.f, 0.f};   // L1: two (unit,b) cells
    float c2 = 0.f;             // L2 final holder

    __syncthreads();

    for (int t = 0; t < NITER; ++t) {
        const int p = t & 1;
        float* const h1r = h1b + p*(4*HP);
        float* const h1w = h1b + (p^1)*(4*HP);
        float* const h2r = h2b + p*(4*HP);
        float* const h2w = h2b + (p^1)*(4*HP);

        if (isL1) {
            if (t < TT) {
                ull acc[4][4];
                #pragma unroll
                for (int g = 0; g < 4; ++g)
                    #pragma unroll
                    for (int b = 0; b < 4; ++b) acc[g][b] = 0ull;
                const float* hp = h1r + ks*28;
                #pragma unroll
                for (int j = 0; j < 7; ++j) {
                    const ulonglong2 u0 = *reinterpret_cast<const ulonglong2*>(hp + 0*HP + 4*j);
                    const ulonglong2 u1 = *reinterpret_cast<const ulonglong2*>(hp + 1*HP + 4*j);
                    const ulonglong2 u2 = *reinterpret_cast<const ulonglong2*>(hp + 2*HP + 4*j);
                    const ulonglong2 u3 = *reinterpret_cast<const ulonglong2*>(hp + 3*HP + 4*j);
                    #pragma unroll
                    for (int g = 0; g < 4; ++g) {
                        acc[g][0] = fma2(w2[g][2*j],   u0.x, acc[g][0]);
                        acc[g][0] = fma2(w2[g][2*j+1], u0.y, acc[g][0]);
                        acc[g][1] = fma2(w2[g][2*j],   u1.x, acc[g][1]);
                        acc[g][1] = fma2(w2[g][2*j+1], u1.y, acc[g][1]);
                        acc[g][2] = fma2(w2[g][2*j],   u2.x, acc[g][2]);
                        acc[g][2] = fma2(w2[g][2*j+1], u2.y, acc[g][2]);
                        acc[g][3] = fma2(w2[g][2*j],   u3.x, acc[g][3]);
                        acc[g][3] = fma2(w2[g][2*j+1], u3.y, acc[g][3]);
                    }
                }
                float z[4][4];
                #pragma unroll
                for (int g = 0; g < 4; ++g)
                    #pragma unroll
                    for (int b = 0; b < 4; ++b) z[g][b] = sum2(acc[g][b]);
                // xor-1 reduce-scatter over k-halves; keep b-pair == ks
                float fin[4][2];
                #pragma unroll
                for (int g = 0; g < 4; ++g)
                    #pragma unroll
                    for (int lb = 0; lb < 2; ++lb) {
                        const float mine  = ks ? z[g][2+lb] : z[g][lb];
                        const float other = ks ? z[g][lb]   : z[g][2+lb];
                        fin[g][lb] = mine + __shfl_xor_sync(pmask, other, 1);
                    }
                #pragma unroll
                for (int lb = 0; lb < 2; ++lb) {
                    const int b = 2*ks + lb;
                    const float xv = xall[b*TT + t];
                    const float zi = fmaf(xv, wx[0], fin[0][lb] + bz[0]);
                    const float zf = fmaf(xv, wx[1], fin[1][lb] + bz[1]);
                    const float zg = fmaf(xv, wx[2], fin[2][lb] + bz[2]);
                    const float zo = fmaf(xv, wx[3], fin[3][lb] + bz[3]);
                    const float ig = sigf(zi), fg = sigf(zf);
                    const float gg = tanhfast(zg), og = sigf(zo);
                    c1[lb] = fmaf(fg, c1[lb], ig*gg);
                    h1w[b*HP + unit] = og * tanhfast(c1[lb]);
                }
            }
        } else if (isL2) {
            if (t >= 1 && t <= TT) {
                ull acc[4][4];
                #pragma unroll
                for (int g = 0; g < 4; ++g)
                    #pragma unroll
                    for (int b = 0; b < 4; ++b) acc[g][b] = 0ull;
                const float* hp = (mat ? h2r : h1r) + ks*28;
                #pragma unroll
                for (int j = 0; j < 7; ++j) {
                    const ulonglong2 u0 = *reinterpret_cast<const ulonglong2*>(hp + 0*HP + 4*j);
                    const ulonglong2 u1 = *reinterpret_cast<const ulonglong2*>(hp + 1*HP + 4*j);
                    const ulonglong2 u2 = *reinterpret_cast<const ulonglong2*>(hp + 2*HP + 4*j);
                    const ulonglong2 u3 = *reinterpret_cast<const ulonglong2*>(hp + 3*HP + 4*j);
                    #pragma unroll
                    for (int g = 0; g < 4; ++g) {
                        acc[g][0] = fma2(w2[g][2*j],   u0.x, acc[g][0]);
                        acc[g][0] = fma2(w2[g][2*j+1], u0.y, acc[g][0]);
                        acc[g][1] = fma2(w2[g][2*j],   u1.x, acc[g][1]);
                        acc[g][1] = fma2(w2[g][2*j+1], u1.y, acc[g][1]);
                        acc[g][2] = fma2(w2[g][2*j],   u2.x, acc[g][2]);
                        acc[g][2] = fma2(w2[g][2*j+1], u2.y, acc[g][2]);
                        acc[g][3] = fma2(w2[g][2*j],   u3.x, acc[g][3]);
                        acc[g][3] = fma2(w2[g][2*j+1], u3.y, acc[g][3]);
                    }
                }
                float z[4][4];
                #pragma unroll
                for (int g = 0; g < 4; ++g)
                    #pragma unroll
                    for (int b = 0; b < 4; ++b) z[g][b] = sum2(acc[g][b]);
                // stage 1: xor-1 over k-halves (partner has same mat); keep b-pair == ks
                float fin1[4][2];
                #pragma unroll
                for (int g = 0; g < 4; ++g)
                    #pragma unroll
                    for (int lb = 0; lb < 2; ++lb) {
                        const float mine  = ks ? z[g][2+lb] : z[g][lb];
                        const float other = ks ? z[g][lb]   : z[g][2+lb];
                        fin1[g][lb] = mine + __shfl_xor_sync(pmask, other, 1);
                    }
                // stage 2: xor-2 over matrices; keep lb == mat; final b = 2*ks + mat
                const int b = 2*ks + mat;
                float zf4[4];
                #pragma unroll
                for (int g = 0; g < 4; ++g) {
                    const float mine  = mat ? fin1[g][1] : fin1[g][0];
                    const float other = mat ? fin1[g][0] : fin1[g][1];
                    zf4[g] = mine + __shfl_xor_sync(qmask, other, 2) + bz[g];
                }
                const float ig = sigf(zf4[0]), fg = sigf(zf4[1]);
                const float gg = tanhfast(zf4[2]), og = sigf(zf4[3]);
                c2 = fmaf(fg, c2, ig*gg);
                h2w[b*HP + unit] = og * tanhfast(c2);
            }
        } else if (isOut) {
            if (t >= 2) {
                float v = 0.f;
                #pragma unroll
                for (int m = 0; m < 26; ++m)
                    v = fmaf(h2r[ob*HP + half*26 + m], wo[m], v);
                v += __shfl_xor_sync(pmask, v, 1);
                if (half == 0) out[(row0 + ob)*TT + (t - 2)] = v + blin;
            }
        }
        __syncthreads();
    }
}

extern "C" void kernel_launch(void* const* d_in, const int* in_sizes, int n_in,
                              void* d_out, int out_size)
{
    const float* input = (const float*)d_in[0];
    const float* W_ih1 = (const float*)d_in[1];
    const float* W_hh1 = (const float*)d_in[2];
    const float* b_ih1 = (const float*)d_in[3];
    const float* b_hh1 = (const float*)d_in[4];
    const float* W_ih2 = (const float*)d_in[5];
    const float* W_hh2 = (const float*)d_in[6];
    const float* b_ih2 = (const float*)d_in[7];
    const float* b_hh2 = (const float*)d_in[8];
    const float* W_lin = (const float*)d_in[9];
    const float* b_lin = (const float*)d_in[10];
    float* out = (float*)d_out;

    lstm2_kernel<<<NBLK, NTH>>>(input, W_ih1, W_hh1, b_ih1, b_hh1,
                                W_ih2, W_hh2, b_ih2, b_hh2,
                                W_lin, b_lin, out);
}